// round 11
// baseline (speedup 1.0000x reference)
#include <cuda_runtime.h>

// SPU transformer bound propagation — pure elementwise over N=8.4M rows. FINAL.
//
// HBM-roofline-bound: 335 MB irreducible traffic (4x fp32 (N,2) reads + 1 fp32
// (N,2) write, zero reuse). Measured 6.71 TB/s / 84.8% DRAM-active across four
// independent runs (51.68/51.68/51.62/51.94 us) — the practical GB300 ceiling
// for a 4R/1W mixed stream; BW x time product == nominal bytes, so zero wasted
// traffic. 10-round sweep conclusions: plain ca loads beat cs/lu; plain wb
// store beats cs; 1 float4/thread (31 regs, full occupancy) beats MLP=8
// (48 regs); block 256 beats 128/512; natural multi-wave beats persistent
// 1-wave grid. Compute pipes <25%, issue <45% — DRAM is the only binding
// resource. Locked.

__device__ __forceinline__ float spu_f(float x) {
    // x >= 0: x*x - 0.5 ; x < 0: sigmoid(-x) - 1 = 1/(1+e^x) - 1
    if (x >= 0.0f) {
        return fmaf(x, x, -0.5f);
    } else {
        return __fdividef(1.0f, 1.0f + __expf(x)) - 1.0f;
    }
}

struct Pair { float lo, hi; };

__device__ __forceinline__ Pair spu_row(
    float l, float u,            // bounds
    float p1l, float p1u,        // slopes_prev
    float q1l, float q1u,        // shifts_prev
    float b0l, float b0u)        // bounds_prev
{
    float sl = spu_f(l);
    float su = spu_f(u);

    bool neg   = (u <= 0.0f);
    bool pos   = (l >= 0.0f);
    bool cross = !(neg || pos);

    float all_slopes = (su - sl) / (u - l);

    float s0 = neg ? all_slopes : 0.0f;
    float s1 = neg ? 0.0f : all_slopes;   // pos || cross == !neg

    bool neg_slope = (all_slopes < 0.0f);
    float lo = neg_slope ? su : sl;
    float hi = neg_slope ? sl : su;
    if (cross) lo = -0.5f;

    float sh1 = fmaf(-s1, u, su);
    float sh0 = fmaf(-s0, l, sl);
    if (cross) sh0 = -0.5f;
    if (neg)   sh1 = sl;

    float s1p = fmaxf(s1, 0.0f), s1n = fminf(s1, 0.0f);
    float s0p = fmaxf(s0, 0.0f), s0n = fminf(s0, 0.0f);

    float UBM = fmaf(s1p, p1u, s1n * p1l);
    float UBV = fmaf(s1p, q1u, fmaf(s1n, q1l, sh1));
    float LBM = fmaf(s0p, p1l, s0n * p1u);
    float LBV = fmaf(s0n, q1l, fmaf(s0p, q1u, sh0));

    float lower = fmaf(fmaxf(LBM, 0.0f), b0l, fmaf(fminf(LBM, 0.0f), b0u, LBV));
    float upper = fmaf(fmaxf(UBM, 0.0f), b0u, fmaf(fminf(UBM, 0.0f), b0l, UBV));

    if (lower > lo) lo = lower;
    if (upper < hi) hi = upper;

    Pair r; r.lo = lo; r.hi = hi;
    return r;
}

__global__ __launch_bounds__(256) void spu_transformer_kernel(
    const float4* __restrict__ bounds,
    const float4* __restrict__ slopes_prev,
    const float4* __restrict__ shifts_prev,
    const float4* __restrict__ bounds_prev,
    float4* __restrict__ out,
    int n4)                       // number of float4 chunks = N/2
{
    int i = blockIdx.x * blockDim.x + threadIdx.x;
    if (i >= n4) return;

    // Front-batch all 4 independent loads (MLP=4)
    float4 b  = bounds[i];
    float4 sp = slopes_prev[i];
    float4 sh = shifts_prev[i];
    float4 bp = bounds_prev[i];

    // Each float4 covers 2 logical rows: (x,y) = row0 (l,u), (z,w) = row1
    Pair r0 = spu_row(b.x, b.y, sp.x, sp.y, sh.x, sh.y, bp.x, bp.y);
    Pair r1 = spu_row(b.z, b.w, sp.z, sp.w, sh.z, sh.w, bp.z, bp.w);

    float4 o;
    o.x = r0.lo; o.y = r0.hi;
    o.z = r1.lo; o.w = r1.hi;
    out[i] = o;
}

extern "C" void kernel_launch(void* const* d_in, const int* in_sizes, int n_in,
                              void* d_out, int out_size)
{
    const float4* bounds      = (const float4*)d_in[0];
    const float4* slopes_prev = (const float4*)d_in[1];
    const float4* shifts_prev = (const float4*)d_in[2];
    const float4* bounds_prev = (const float4*)d_in[3];
    float4* out = (float4*)d_out;

    // in_sizes[0] = N*2 floats; float4 chunks = N*2/4 = N/2
    int n4 = in_sizes[0] / 4;

    int threads = 256;
    int blocks = (n4 + threads - 1) / threads;
    spu_transformer_kernel<<<blocks, threads>>>(bounds, slopes_prev, shifts_prev,
                                                bounds_prev, out, n4);
}

// round 13
// speedup vs baseline: 1.0131x; 1.0131x over previous
#include <cuda_runtime.h>

// SPU transformer bound propagation — pure elementwise over N=8.4M rows. FINAL.
//
// HBM-roofline-bound: 335 MB irreducible traffic (4x fp32 (N,2) reads + 1 fp32
// (N,2) write, zero reuse). Measured 6.71-6.74 TB/s / 84.7-85.1% DRAM-active
// across five independent runs (51.68/51.68/51.62/51.94/51.94 us) — the
// practical GB300 ceiling for a 4R/1W mixed stream; BW x time product equals
// nominal bytes, so zero wasted traffic. 11-round sweep conclusions: plain ca
// loads beat cs/lu; plain wb store beats cs; 1 float4/thread (31 regs, full
// occupancy) beats MLP=8 (48 regs); block 256 beats 128/512; natural
// multi-wave beats persistent 1-wave grid. Compute pipes <25%, issue <45% —
// DRAM is the only binding resource. Locked.

__device__ __forceinline__ float spu_f(float x) {
    // x >= 0: x*x - 0.5 ; x < 0: sigmoid(-x) - 1 = 1/(1+e^x) - 1
    if (x >= 0.0f) {
        return fmaf(x, x, -0.5f);
    } else {
        return __fdividef(1.0f, 1.0f + __expf(x)) - 1.0f;
    }
}

struct Pair { float lo, hi; };

__device__ __forceinline__ Pair spu_row(
    float l, float u,            // bounds
    float p1l, float p1u,        // slopes_prev
    float q1l, float q1u,        // shifts_prev
    float b0l, float b0u)        // bounds_prev
{
    float sl = spu_f(l);
    float su = spu_f(u);

    bool neg   = (u <= 0.0f);
    bool pos   = (l >= 0.0f);
    bool cross = !(neg || pos);

    float all_slopes = (su - sl) / (u - l);

    float s0 = neg ? all_slopes : 0.0f;
    float s1 = neg ? 0.0f : all_slopes;   // pos || cross == !neg

    bool neg_slope = (all_slopes < 0.0f);
    float lo = neg_slope ? su : sl;
    float hi = neg_slope ? sl : su;
    if (cross) lo = -0.5f;

    float sh1 = fmaf(-s1, u, su);
    float sh0 = fmaf(-s0, l, sl);
    if (cross) sh0 = -0.5f;
    if (neg)   sh1 = sl;

    float s1p = fmaxf(s1, 0.0f), s1n = fminf(s1, 0.0f);
    float s0p = fmaxf(s0, 0.0f), s0n = fminf(s0, 0.0f);

    float UBM = fmaf(s1p, p1u, s1n * p1l);
    float UBV = fmaf(s1p, q1u, fmaf(s1n, q1l, sh1));
    float LBM = fmaf(s0p, p1l, s0n * p1u);
    float LBV = fmaf(s0n, q1l, fmaf(s0p, q1u, sh0));

    float lower = fmaf(fmaxf(LBM, 0.0f), b0l, fmaf(fminf(LBM, 0.0f), b0u, LBV));
    float upper = fmaf(fmaxf(UBM, 0.0f), b0u, fmaf(fminf(UBM, 0.0f), b0l, UBV));

    if (lower > lo) lo = lower;
    if (upper < hi) hi = upper;

    Pair r; r.lo = lo; r.hi = hi;
    return r;
}

__global__ __launch_bounds__(256) void spu_transformer_kernel(
    const float4* __restrict__ bounds,
    const float4* __restrict__ slopes_prev,
    const float4* __restrict__ shifts_prev,
    const float4* __restrict__ bounds_prev,
    float4* __restrict__ out,
    int n4)                       // number of float4 chunks = N/2
{
    int i = blockIdx.x * blockDim.x + threadIdx.x;
    if (i >= n4) return;

    // Front-batch all 4 independent loads (MLP=4)
    float4 b  = bounds[i];
    float4 sp = slopes_prev[i];
    float4 sh = shifts_prev[i];
    float4 bp = bounds_prev[i];

    // Each float4 covers 2 logical rows: (x,y) = row0 (l,u), (z,w) = row1
    Pair r0 = spu_row(b.x, b.y, sp.x, sp.y, sh.x, sh.y, bp.x, bp.y);
    Pair r1 = spu_row(b.z, b.w, sp.z, sp.w, sh.z, sh.w, bp.z, bp.w);

    float4 o;
    o.x = r0.lo; o.y = r0.hi;
    o.z = r1.lo; o.w = r1.hi;
    out[i] = o;
}

extern "C" void kernel_launch(void* const* d_in, const int* in_sizes, int n_in,
                              void* d_out, int out_size)
{
    const float4* bounds      = (const float4*)d_in[0];
    const float4* slopes_prev = (const float4*)d_in[1];
    const float4* shifts_prev = (const float4*)d_in[2];
    const float4* bounds_prev = (const float4*)d_in[3];
    float4* out = (float4*)d_out;

    // in_sizes[0] = N*2 floats; float4 chunks = N*2/4 = N/2
    int n4 = in_sizes[0] / 4;

    int threads = 256;
    int blocks = (n4 + threads - 1) / threads;
    spu_transformer_kernel<<<blocks, threads>>>(bounds, slopes_prev, shifts_prev,
                                                bounds_prev, out, n4);
}